// round 4
// baseline (speedup 1.0000x reference)
#include <cuda_runtime.h>
#include <cstdint>

// 2-layer LSTM (H=50) + FC. B=4096, T=512, in-dim 1.
// R3: h and x stored PRE-DUPLICATED as (v,v) u64 pairs in smem, so the
// inner loop is pure {3x ld.shared.v2.u64, 8x fma.rn.f32x2} - no packing movs.
// Mapping: bg = tid&7 (4 batches), j = tid>>3 (hidden unit). Weight loads
// broadcast (4 addr/warp, 1 wavefront); dup-h loads are 2 conflict-free wf.

typedef unsigned long long u64;

#define HID   50
#define BT    32
#define NT    400
#define TLEN  512

// byte offsets into dynamic smem
#define OFF_WP0 0          // packed w_hh0  [50j][50k] float4 = 40000
#define OFF_WPA 40000      // packed w_ih1
#define OFF_WPB 80000      // packed w_hh1
#define OFF_H1  120000     // h1 dup double-buffer: 2 x (50k x 8bg x 32B = 12800)
#define OFF_H2  145600     // h2 dup double-buffer
#define OFF_XS  171200     // x dup chunk: 64 steps x 8bg x 32B = 16384
#define OFF_B0  187584     // packed bias l1: float4[50]
#define OFF_B1  188384     // packed bias l2
#define OFF_WX  189184     // packed w_ih0: float4[50]
#define OFF_FCW 189984     // fc weights: 50 floats
#define SMEM_BYTES 190208

#define HBUF 12800         // bytes per dup h buffer

__device__ __forceinline__ u64 pk2(float lo, float hi) {
    u64 r; asm("mov.b64 %0, {%1, %2};" : "=l"(r) : "f"(lo), "f"(hi)); return r;
}
__device__ __forceinline__ void upk2(u64 v, float& lo, float& hi) {
    asm("mov.b64 {%0, %1}, %2;" : "=f"(lo), "=f"(hi) : "l"(v));
}
__device__ __forceinline__ void ffma2(u64& d, u64 a, u64 b) {
    asm("fma.rn.f32x2 %0, %1, %2, %0;" : "+l"(d) : "l"(a), "l"(b));
}
__device__ __forceinline__ float fsig(float v) {
    return __fdividef(1.0f, 1.0f + __expf(-v));
}
__device__ __forceinline__ float ftanh(float v) {
    return __fdividef(2.0f, 1.0f + __expf(-2.0f * v)) - 1.0f;
}

// 50-step gate-packed GEMV on duplicated h: acc += W[j][k] * h[k]
// wa: weight row (16B per k). ha: dup-h base (256B per k, this thread's bg).
__device__ __forceinline__ void gemm50d(uint32_t wa, uint32_t ha,
                                        u64 aif[4], u64 ago[4]) {
#pragma unroll
    for (int k = 0; k < HID; ++k) {
        u64 wif, wgo, h0d, h1d, h2d, h3d;
        asm volatile("ld.shared.v2.u64 {%0, %1}, [%2];"
                     : "=l"(wif), "=l"(wgo) : "r"(wa + 16u * k));
        asm volatile("ld.shared.v2.u64 {%0, %1}, [%2];"
                     : "=l"(h0d), "=l"(h1d) : "r"(ha + 256u * k));
        asm volatile("ld.shared.v2.u64 {%0, %1}, [%2];"
                     : "=l"(h2d), "=l"(h3d) : "r"(ha + 256u * k + 16u));
        ffma2(aif[0], wif, h0d); ffma2(ago[0], wgo, h0d);
        ffma2(aif[1], wif, h1d); ffma2(ago[1], wgo, h1d);
        ffma2(aif[2], wif, h2d); ffma2(ago[2], wgo, h2d);
        ffma2(aif[3], wif, h3d); ffma2(ago[3], wgo, h3d);
    }
}

__device__ __forceinline__ void act_update(const u64 aif[4], const u64 ago[4],
                                           float c[4], float hv[4]) {
#pragma unroll
    for (int r = 0; r < 4; ++r) {
        float pi, pf, pg, po;
        upk2(aif[r], pi, pf);
        upk2(ago[r], pg, po);
        float iv = fsig(pi);
        float fv = fsig(pf);
        float gv = ftanh(pg);
        float ov = fsig(po);
        c[r]  = fv * c[r] + iv * gv;
        hv[r] = ov * ftanh(c[r]);
    }
}

// store 4 h values duplicated: [addr] = {(h0,h0),(h1,h1)}, [addr+16] = {(h2,h2),(h3,h3)}
__device__ __forceinline__ void st_dup4(uint32_t addr, const float hv[4]) {
    u64 d0 = pk2(hv[0], hv[0]), d1 = pk2(hv[1], hv[1]);
    u64 d2 = pk2(hv[2], hv[2]), d3 = pk2(hv[3], hv[3]);
    asm volatile("st.shared.v2.u64 [%0], {%1, %2};" :: "r"(addr), "l"(d0), "l"(d1));
    asm volatile("st.shared.v2.u64 [%0], {%1, %2};" :: "r"(addr + 16u), "l"(d2), "l"(d3));
}

extern __shared__ float smem[];

__global__ __launch_bounds__(NT, 1) void lstm2_kernel(
    const float* __restrict__ x,
    const float* __restrict__ w_ih0, const float* __restrict__ w_hh0,
    const float* __restrict__ b_ih0, const float* __restrict__ b_hh0,
    const float* __restrict__ w_ih1, const float* __restrict__ w_hh1,
    const float* __restrict__ b_ih1, const float* __restrict__ b_hh1,
    const float* __restrict__ fc_w,  const float* __restrict__ fc_b,
    float* __restrict__ out)
{
    char* sb = (char*)smem;
    const uint32_t sa = (uint32_t)__cvta_generic_to_shared(smem);
    const int tid   = threadIdx.x;
    const int bbase = blockIdx.x * BT;

    // ---- stage packed weights: wp[j][k] = (Wi[j][k], Wf, Wg, Wo) ----
    {
        float4* wp0 = (float4*)(sb + OFF_WP0);
        float4* wpA = (float4*)(sb + OFF_WPA);
        float4* wpB = (float4*)(sb + OFF_WPB);
        for (int idx = tid; idx < HID * HID; idx += NT) {
            int jj = idx / HID, kk = idx - jj * HID;
            int r0 = jj * HID + kk;
            wp0[idx] = make_float4(w_hh0[r0], w_hh0[r0 + 50 * HID],
                                   w_hh0[r0 + 100 * HID], w_hh0[r0 + 150 * HID]);
            wpA[idx] = make_float4(w_ih1[r0], w_ih1[r0 + 50 * HID],
                                   w_ih1[r0 + 100 * HID], w_ih1[r0 + 150 * HID]);
            wpB[idx] = make_float4(w_hh1[r0], w_hh1[r0 + 50 * HID],
                                   w_hh1[r0 + 100 * HID], w_hh1[r0 + 150 * HID]);
        }
        float4* b0p = (float4*)(sb + OFF_B0);
        float4* b1p = (float4*)(sb + OFF_B1);
        float4* wxp = (float4*)(sb + OFF_WX);
        float*  fcs = (float*)(sb + OFF_FCW);
        for (int g = tid; g < HID; g += NT) {
            b0p[g] = make_float4(b_ih0[g]       + b_hh0[g],
                                 b_ih0[g + 50]  + b_hh0[g + 50],
                                 b_ih0[g + 100] + b_hh0[g + 100],
                                 b_ih0[g + 150] + b_hh0[g + 150]);
            b1p[g] = make_float4(b_ih1[g]       + b_hh1[g],
                                 b_ih1[g + 50]  + b_hh1[g + 50],
                                 b_ih1[g + 100] + b_hh1[g + 100],
                                 b_ih1[g + 150] + b_hh1[g + 150]);
            wxp[g] = make_float4(w_ih0[g], w_ih0[g + 50],
                                 w_ih0[g + 100], w_ih0[g + 150]);
            fcs[g] = fc_w[g];
        }
        // zero both dup h double-buffers (h1 + h2 = 51200 B = 6400 u64)
        u64* hz = (u64*)(sb + OFF_H1);
        for (int idx = tid; idx < 6400; idx += NT) hz[idx] = 0ull;
    }
    __syncthreads();

    // ---- per-thread mapping ----
    const int bg = tid & 7;     // batch group: batches 4*bg .. 4*bg+3
    const int j  = tid >> 3;    // hidden unit (0..49)

    u64 b0if, b0go, b1if, b1go, wxif, wxgo;
    {
        float4 t4 = ((float4*)(sb + OFF_B0))[j];
        b0if = pk2(t4.x, t4.y); b0go = pk2(t4.z, t4.w);
        t4 = ((float4*)(sb + OFF_B1))[j];
        b1if = pk2(t4.x, t4.y); b1go = pk2(t4.z, t4.w);
        t4 = ((float4*)(sb + OFF_WX))[j];
        wxif = pk2(t4.x, t4.y); wxgo = pk2(t4.z, t4.w);
    }

    const uint32_t wa0 = sa + OFF_WP0 + (uint32_t)j * 800u;
    const uint32_t waA = sa + OFF_WPA + (uint32_t)j * 800u;
    const uint32_t waB = sa + OFF_WPB + (uint32_t)j * 800u;
    const uint32_t h1rd = sa + OFF_H1 + (uint32_t)bg * 32u;
    const uint32_t h2rd = sa + OFF_H2 + (uint32_t)bg * 32u;
    const uint32_t xrd  = sa + OFF_XS + (uint32_t)bg * 32u;
    const uint32_t h1wbase = sa + OFF_H1 + (uint32_t)j * 256u + (uint32_t)bg * 32u;
    const uint32_t h2wbase = sa + OFF_H2 + (uint32_t)j * 256u + (uint32_t)bg * 32u;

    float c1[4] = {0.f, 0.f, 0.f, 0.f};
    float c2[4] = {0.f, 0.f, 0.f, 0.f};
    float h1v[4], h2v[4];

    for (int t = 0; t < TLEN; ++t) {
        // stage 64-step x chunk, duplicated (coalesced gmem reads)
        if ((t & 63) == 0) {
            u64* xs = (u64*)(sb + OFF_XS);
            for (int idx = tid; idx < BT * 64; idx += NT) {
                int b = idx >> 6, tt = idx & 63;
                float xv = x[(bbase + b) * TLEN + t + tt];
                xs[tt * 32 + (b >> 2) * 4 + (b & 3)] = pk2(xv, xv);
            }
            __syncthreads();
        }

        const uint32_t cur = (uint32_t)(t & 1) * HBUF;
        const uint32_t nxt = HBUF - cur;

        // ============ layer 1 ============
        u64 aif[4], ago[4];
        {
            u64 x0d, x1d, x2d, x3d;
            const uint32_t xa = xrd + (uint32_t)(t & 63) * 256u;
            asm volatile("ld.shared.v2.u64 {%0, %1}, [%2];"
                         : "=l"(x0d), "=l"(x1d) : "r"(xa));
            asm volatile("ld.shared.v2.u64 {%0, %1}, [%2];"
                         : "=l"(x2d), "=l"(x3d) : "r"(xa + 16u));
            aif[0] = b0if; ffma2(aif[0], wxif, x0d);
            ago[0] = b0go; ffma2(ago[0], wxgo, x0d);
            aif[1] = b0if; ffma2(aif[1], wxif, x1d);
            ago[1] = b0go; ffma2(ago[1], wxgo, x1d);
            aif[2] = b0if; ffma2(aif[2], wxif, x2d);
            ago[2] = b0go; ffma2(ago[2], wxgo, x2d);
            aif[3] = b0if; ffma2(aif[3], wxif, x3d);
            ago[3] = b0go; ffma2(ago[3], wxgo, x3d);
        }
        gemm50d(wa0, h1rd + cur, aif, ago);
        act_update(aif, ago, c1, h1v);
        st_dup4(h1wbase + nxt, h1v);
        __syncthreads();

        // ============ layer 2 ============
        aif[0] = b1if; aif[1] = b1if; aif[2] = b1if; aif[3] = b1if;
        ago[0] = b1go; ago[1] = b1go; ago[2] = b1go; ago[3] = b1go;
        gemm50d(waA, h1rd + nxt, aif, ago);   // input path: new h1
        gemm50d(waB, h2rd + cur, aif, ago);   // recurrent path: old h2
        act_update(aif, ago, c2, h2v);
        st_dup4(h2wbase + nxt, h2v);
        __syncthreads();
    }

    // ---- final FC (last h2 lives in buffer 0 after t=511) ----
    if (tid < BT) {
        const char* h2f = sb + OFF_H2;
        const float* fcs = (const float*)(sb + OFF_FCW);
        const int b = tid;
        float s = fc_b[0];
#pragma unroll 10
        for (int k = 0; k < HID; ++k)
            s += *(const float*)(h2f + k * 256 + (b >> 2) * 32 + (b & 3) * 8) * fcs[k];
        out[bbase + b] = s;
    }
}

extern "C" void kernel_launch(void* const* d_in, const int* in_sizes, int n_in,
                              void* d_out, int out_size) {
    const float* x     = (const float*)d_in[0];
    const float* w_ih0 = (const float*)d_in[1];
    const float* w_hh0 = (const float*)d_in[2];
    const float* b_ih0 = (const float*)d_in[3];
    const float* b_hh0 = (const float*)d_in[4];
    const float* w_ih1 = (const float*)d_in[5];
    const float* w_hh1 = (const float*)d_in[6];
    const float* b_ih1 = (const float*)d_in[7];
    const float* b_hh1 = (const float*)d_in[8];
    const float* fc_w  = (const float*)d_in[9];
    const float* fc_b  = (const float*)d_in[10];
    float* out = (float*)d_out;

    cudaFuncSetAttribute(lstm2_kernel,
                         cudaFuncAttributeMaxDynamicSharedMemorySize,
                         SMEM_BYTES);

    lstm2_kernel<<<4096 / BT, NT, SMEM_BYTES>>>(
        x, w_ih0, w_hh0, b_ih0, b_hh0,
        w_ih1, w_hh1, b_ih1, b_hh1, fc_w, fc_b, out);
}

// round 6
// speedup vs baseline: 2.1492x; 2.1492x over previous
#include <cuda_runtime.h>
#include <cstdint>

// 2-layer LSTM (H=50) + FC. B=4096, T=512, in-dim 1.
// R5: NT=832 (26 warps = 13 clean kid pairs; R4's 25-warp pairing bug fixed).
// k-split across two warp-uniform halves (kid); each (j,bg) pair computes
// half the k-sum; halves merged via smem partials. Inner loop: 1x LDS.128
// weights (broadcast) + 1x LDS.128 h (conflict-free) + 4 movs + 8 fma.rn.f32x2.

typedef unsigned long long u64;

#define HID   50
#define BT    32
#define NT    832
#define TLEN  512

// byte offsets into dynamic smem
#define OFF_WP0 0          // packed w_hh0  [50j][50k] float4 = 40000
#define OFF_WPA 40000      // packed w_ih1
#define OFF_WPB 80000      // packed w_hh1
#define OFF_H1  120000     // h1 double buffer: 2 x (50k * 32b * 4B = 6400)
#define OFF_H2  132800     // h2 double buffer
#define OFF_XS  145600     // x chunk: 64 steps x 32 batches x 4 = 8192
#define OFF_RED 153792     // reduction partials: 400 slots x 80B = 32000
#define OFF_B0  185792     // packed bias l1: float4[50]
#define OFF_B1  186592     // packed bias l2
#define OFF_WX  187392     // packed w_ih0: float4[50]
#define OFF_FCW 188192     // fc weights: 50 floats
#define SMEM_BYTES 188416

#define HBUF 6400          // bytes per h buffer

__device__ __forceinline__ u64 pk2(float lo, float hi) {
    u64 r; asm("mov.b64 %0, {%1, %2};" : "=l"(r) : "f"(lo), "f"(hi)); return r;
}
__device__ __forceinline__ void upk2(u64 v, float& lo, float& hi) {
    asm("mov.b64 {%0, %1}, %2;" : "=f"(lo), "=f"(hi) : "l"(v));
}
__device__ __forceinline__ void ffma2(u64& d, u64 a, u64 b) {
    asm("fma.rn.f32x2 %0, %1, %2, %0;" : "+l"(d) : "l"(a), "l"(b));
}
__device__ __forceinline__ void fadd2(u64& d, u64 a) {
    asm("add.rn.f32x2 %0, %0, %1;" : "+l"(d) : "l"(a));
}
__device__ __forceinline__ float fsig(float v) {
    return __fdividef(1.0f, 1.0f + __expf(-v));
}
__device__ __forceinline__ float ftanh(float v) {
    return __fdividef(2.0f, 1.0f + __expf(-2.0f * v)) - 1.0f;
}

// 25-step gate-packed GEMV: acc += W[j][k] * h[k] for this thread's k-half.
__device__ __forceinline__ void gemm25(const char* __restrict__ wb,
                                       const char* __restrict__ hb,
                                       u64 aif[4], u64 ago[4]) {
#pragma unroll
    for (int k = 0; k < 25; ++k) {
        ulonglong2 w = *(const ulonglong2*)(wb + 16 * k);
        float4 h = *(const float4*)(hb + 128 * k);
        u64 hh;
        hh = pk2(h.x, h.x); ffma2(aif[0], w.x, hh); ffma2(ago[0], w.y, hh);
        hh = pk2(h.y, h.y); ffma2(aif[1], w.x, hh); ffma2(ago[1], w.y, hh);
        hh = pk2(h.z, h.z); ffma2(aif[2], w.x, hh); ffma2(ago[2], w.y, hh);
        hh = pk2(h.w, h.w); ffma2(aif[3], w.x, hh); ffma2(ago[3], w.y, hh);
    }
}

__device__ __forceinline__ void act_update(const u64 aif[4], const u64 ago[4],
                                           float c[4], float hv[4]) {
#pragma unroll
    for (int r = 0; r < 4; ++r) {
        float pi, pf, pg, po;
        upk2(aif[r], pi, pf);
        upk2(ago[r], pg, po);
        float iv = fsig(pi);
        float fv = fsig(pf);
        float gv = ftanh(pg);
        float ov = fsig(po);
        c[r]  = fv * c[r] + iv * gv;
        hv[r] = ov * ftanh(c[r]);
    }
}

__device__ __forceinline__ void red_store(char* rp, const u64 aif[4],
                                          const u64 ago[4]) {
    ((ulonglong2*)rp)[0] = make_ulonglong2(aif[0], aif[1]);
    ((ulonglong2*)rp)[1] = make_ulonglong2(aif[2], aif[3]);
    ((ulonglong2*)rp)[2] = make_ulonglong2(ago[0], ago[1]);
    ((ulonglong2*)rp)[3] = make_ulonglong2(ago[2], ago[3]);
}
__device__ __forceinline__ void red_add(const char* rp, u64 aif[4], u64 ago[4]) {
    ulonglong2 p0 = ((const ulonglong2*)rp)[0];
    ulonglong2 p1 = ((const ulonglong2*)rp)[1];
    ulonglong2 p2 = ((const ulonglong2*)rp)[2];
    ulonglong2 p3 = ((const ulonglong2*)rp)[3];
    fadd2(aif[0], p0.x); fadd2(aif[1], p0.y);
    fadd2(aif[2], p1.x); fadd2(aif[3], p1.y);
    fadd2(ago[0], p2.x); fadd2(ago[1], p2.y);
    fadd2(ago[2], p3.x); fadd2(ago[3], p3.y);
}

extern __shared__ float smem[];

__global__ __launch_bounds__(NT, 1) void lstm2_kernel(
    const float* __restrict__ x,
    const float* __restrict__ w_ih0, const float* __restrict__ w_hh0,
    const float* __restrict__ b_ih0, const float* __restrict__ b_hh0,
    const float* __restrict__ w_ih1, const float* __restrict__ w_hh1,
    const float* __restrict__ b_ih1, const float* __restrict__ b_hh1,
    const float* __restrict__ fc_w,  const float* __restrict__ fc_b,
    float* __restrict__ out)
{
    char* sb = (char*)smem;
    const int tid   = threadIdx.x;
    const int bbase = blockIdx.x * BT;

    // ---- stage packed weights: wp[j][k] = (Wi[j][k], Wf, Wg, Wo) ----
    {
        float4* wp0 = (float4*)(sb + OFF_WP0);
        float4* wpA = (float4*)(sb + OFF_WPA);
        float4* wpB = (float4*)(sb + OFF_WPB);
        for (int idx = tid; idx < HID * HID; idx += NT) {
            int jj = idx / HID, kk = idx - jj * HID;
            int r0 = jj * HID + kk;
            wp0[idx] = make_float4(w_hh0[r0], w_hh0[r0 + 50 * HID],
                                   w_hh0[r0 + 100 * HID], w_hh0[r0 + 150 * HID]);
            wpA[idx] = make_float4(w_ih1[r0], w_ih1[r0 + 50 * HID],
                                   w_ih1[r0 + 100 * HID], w_ih1[r0 + 150 * HID]);
            wpB[idx] = make_float4(w_hh1[r0], w_hh1[r0 + 50 * HID],
                                   w_hh1[r0 + 100 * HID], w_hh1[r0 + 150 * HID]);
        }
        float4* b0p = (float4*)(sb + OFF_B0);
        float4* b1p = (float4*)(sb + OFF_B1);
        float4* wxp = (float4*)(sb + OFF_WX);
        float*  fcs = (float*)(sb + OFF_FCW);
        for (int g = tid; g < HID; g += NT) {
            b0p[g] = make_float4(b_ih0[g]       + b_hh0[g],
                                 b_ih0[g + 50]  + b_hh0[g + 50],
                                 b_ih0[g + 100] + b_hh0[g + 100],
                                 b_ih0[g + 150] + b_hh0[g + 150]);
            b1p[g] = make_float4(b_ih1[g]       + b_hh1[g],
                                 b_ih1[g + 50]  + b_hh1[g + 50],
                                 b_ih1[g + 100] + b_hh1[g + 100],
                                 b_ih1[g + 150] + b_hh1[g + 150]);
            wxp[g] = make_float4(w_ih0[g], w_ih0[g + 50],
                                 w_ih0[g + 100], w_ih0[g + 150]);
            fcs[g] = fc_w[g];
        }
        float* hz = (float*)(sb + OFF_H1);
        for (int idx = tid; idx < 6400; idx += NT) hz[idx] = 0.0f;  // h1+h2 bufs
    }
    __syncthreads();

    // ---- mapping: even/odd warp pairs share rem; kid warp-uniform ----
    const int lane = tid & 31;
    const int kid  = (tid >> 5) & 1;              // k-half
    const int rem  = ((tid >> 6) << 5) | lane;    // 0..415
    const bool active = (rem < 400);
    const int bg   = rem & 7;                     // batch group (4 batches)
    const int jj   = active ? (rem >> 3) : 0;     // hidden unit 0..49

    u64 b0if, b0go, b1if, b1go, wxif, wxgo;
    {
        float4 t4 = ((float4*)(sb + OFF_B0))[jj];
        b0if = pk2(t4.x, t4.y); b0go = pk2(t4.z, t4.w);
        t4 = ((float4*)(sb + OFF_B1))[jj];
        b1if = pk2(t4.x, t4.y); b1go = pk2(t4.z, t4.w);
        t4 = ((float4*)(sb + OFF_WX))[jj];
        wxif = pk2(t4.x, t4.y); wxgo = pk2(t4.z, t4.w);
    }

    const char* w0p = sb + OFF_WP0 + jj * 800 + kid * 400;
    const char* wAp = sb + OFF_WPA + jj * 800 + kid * 400;
    const char* wBp = sb + OFF_WPB + jj * 800 + kid * 400;
    const int   hoff = bg * 16 + kid * 3200;      // bg offset + k-half offset
    char*       redp = sb + OFF_RED + rem * 80;
    const char* xrd  = sb + OFF_XS + bg * 16;

    float c1[4] = {0.f, 0.f, 0.f, 0.f};
    float c2[4] = {0.f, 0.f, 0.f, 0.f};
    float h1v[4], h2v[4];

    for (int t = 0; t < TLEN; ++t) {
        // stage 64-step x chunk (coalesced)
        if ((t & 63) == 0) {
            float* xs = (float*)(sb + OFF_XS);
            for (int idx = tid; idx < BT * 64; idx += NT) {
                int b = idx >> 6, tt = idx & 63;
                xs[tt * BT + b] = x[(bbase + b) * TLEN + t + tt];
            }
            __syncthreads();
        }

        const int cur = (t & 1) * HBUF;
        const int nxt = HBUF - cur;

        // ============ layer 1 ============
        u64 aif[4], ago[4];
        if (active) {
            if (kid == 0) {
                float4 xv = *(const float4*)(xrd + (t & 63) * 128);
                u64 hh;
                hh = pk2(xv.x, xv.x); aif[0] = b0if; ffma2(aif[0], wxif, hh);
                                      ago[0] = b0go; ffma2(ago[0], wxgo, hh);
                hh = pk2(xv.y, xv.y); aif[1] = b0if; ffma2(aif[1], wxif, hh);
                                      ago[1] = b0go; ffma2(ago[1], wxgo, hh);
                hh = pk2(xv.z, xv.z); aif[2] = b0if; ffma2(aif[2], wxif, hh);
                                      ago[2] = b0go; ffma2(ago[2], wxgo, hh);
                hh = pk2(xv.w, xv.w); aif[3] = b0if; ffma2(aif[3], wxif, hh);
                                      ago[3] = b0go; ffma2(ago[3], wxgo, hh);
            } else {
                aif[0] = aif[1] = aif[2] = aif[3] = 0ull;
                ago[0] = ago[1] = ago[2] = ago[3] = 0ull;
            }
            gemm25(w0p, sb + OFF_H1 + cur + hoff, aif, ago);
            if (kid) red_store(redp, aif, ago);
        }
        __syncthreads();
        if (active && !kid) {
            red_add(redp, aif, ago);
            act_update(aif, ago, c1, h1v);
            *(float4*)(sb + OFF_H1 + nxt + jj * 128 + bg * 16) =
                make_float4(h1v[0], h1v[1], h1v[2], h1v[3]);
        }
        __syncthreads();

        // ============ layer 2 ============
        if (active) {
            if (kid == 0) {
                aif[0] = b1if; aif[1] = b1if; aif[2] = b1if; aif[3] = b1if;
                ago[0] = b1go; ago[1] = b1go; ago[2] = b1go; ago[3] = b1go;
            } else {
                aif[0] = aif[1] = aif[2] = aif[3] = 0ull;
                ago[0] = ago[1] = ago[2] = ago[3] = 0ull;
            }
            gemm25(wAp, sb + OFF_H1 + nxt + hoff, aif, ago);   // in: new h1
            gemm25(wBp, sb + OFF_H2 + cur + hoff, aif, ago);   // rec: old h2
            if (kid) red_store(redp, aif, ago);
        }
        __syncthreads();
        if (active && !kid) {
            red_add(redp, aif, ago);
            act_update(aif, ago, c2, h2v);
            *(float4*)(sb + OFF_H2 + nxt + jj * 128 + bg * 16) =
                make_float4(h2v[0], h2v[1], h2v[2], h2v[3]);
        }
        __syncthreads();
    }

    // ---- final FC (last h2 lives in buffer 0 after t=511) ----
    if (tid < BT) {
        const float* h2f = (const float*)(sb + OFF_H2);
        const float* fcs = (const float*)(sb + OFF_FCW);
        float s = fc_b[0];
#pragma unroll 10
        for (int k = 0; k < HID; ++k) s += h2f[k * BT + tid] * fcs[k];
        out[bbase + tid] = s;
    }
}

extern "C" void kernel_launch(void* const* d_in, const int* in_sizes, int n_in,
                              void* d_out, int out_size) {
    const float* x     = (const float*)d_in[0];
    const float* w_ih0 = (const float*)d_in[1];
    const float* w_hh0 = (const float*)d_in[2];
    const float* b_ih0 = (const float*)d_in[3];
    const float* b_hh0 = (const float*)d_in[4];
    const float* w_ih1 = (const float*)d_in[5];
    const float* w_hh1 = (const float*)d_in[6];
    const float* b_ih1 = (const float*)d_in[7];
    const float* b_hh1 = (const float*)d_in[8];
    const float* fc_w  = (const float*)d_in[9];
    const float* fc_b  = (const float*)d_in[10];
    float* out = (float*)d_out;

    cudaFuncSetAttribute(lstm2_kernel,
                         cudaFuncAttributeMaxDynamicSharedMemorySize,
                         SMEM_BYTES);

    lstm2_kernel<<<4096 / BT, NT, SMEM_BYTES>>>(
        x, w_ih0, w_hh0, b_ih0, b_hh0,
        w_ih1, w_hh1, b_ih1, b_hh1, fc_w, fc_b, out);
}

// round 7
// speedup vs baseline: 2.3068x; 1.0733x over previous
#include <cuda_runtime.h>
#include <cstdint>

// 2-layer LSTM (H=50) + FC. B=4096, T=512, in-dim 1.
// R6 = R2 (best known: 400 thr, gate-packed f32x2, bcast weights, v4 h loads)
// with NON-VOLATILE inner-loop loads + explicit +1 prefetch so ptxas can
// software-pipeline LDS latency under the 8 FFMA2 chains.

typedef unsigned long long u64;

#define HID   50
#define BT    32
#define NT    400
#define TLEN  512

// byte offsets into dynamic smem
#define OFF_WP0 0          // packed w_hh0  [50j][50k] float4 = 40000
#define OFF_WPA 40000      // packed w_ih1
#define OFF_WPB 80000      // packed w_hh1
#define OFF_H1  120000     // h1 double buffer: 2 x (50k * 32b * 4B = 6400)
#define OFF_H2  132800     // h2 double buffer
#define OFF_XS  145600     // x chunk: 64 steps x 32 batches x 4 = 8192
#define OFF_B0  153792     // packed bias l1: float4[50]
#define OFF_B1  154592     // packed bias l2
#define OFF_WX  155392     // packed w_ih0: float4[50]
#define OFF_FCW 156192     // fc weights: 50 floats
#define SMEM_BYTES 156416

#define HBUF 6400          // bytes per h buffer

__device__ __forceinline__ u64 pk2(float lo, float hi) {
    u64 r; asm("mov.b64 %0, {%1, %2};" : "=l"(r) : "f"(lo), "f"(hi)); return r;
}
__device__ __forceinline__ void upk2(u64 v, float& lo, float& hi) {
    asm("mov.b64 {%0, %1}, %2;" : "=f"(lo), "=f"(hi) : "l"(v));
}
__device__ __forceinline__ void ffma2(u64& d, u64 a, u64 b) {
    asm("fma.rn.f32x2 %0, %1, %2, %0;" : "+l"(d) : "l"(a), "l"(b));
}
__device__ __forceinline__ float fsig(float v) {
    return __fdividef(1.0f, 1.0f + __expf(-v));
}
__device__ __forceinline__ float ftanh(float v) {
    return __fdividef(2.0f, 1.0f + __expf(-2.0f * v)) - 1.0f;
}

// 50-step gate-packed GEMV with +1 software prefetch (plain loads so ptxas
// may hoist/pipeline further).
__device__ __forceinline__ void gemm50(const char* __restrict__ wb,
                                       const char* __restrict__ hb,
                                       u64 aif[4], u64 ago[4]) {
    ulonglong2 w = *(const ulonglong2*)wb;
    float4     h = *(const float4*)hb;
#pragma unroll
    for (int k = 0; k < HID; ++k) {
        ulonglong2 wn;
        float4     hn;
        if (k + 1 < HID) {
            wn = *(const ulonglong2*)(wb + 16 * (k + 1));
            hn = *(const float4*)(hb + 128 * (k + 1));
        }
        u64 hh;
        hh = pk2(h.x, h.x); ffma2(aif[0], w.x, hh); ffma2(ago[0], w.y, hh);
        hh = pk2(h.y, h.y); ffma2(aif[1], w.x, hh); ffma2(ago[1], w.y, hh);
        hh = pk2(h.z, h.z); ffma2(aif[2], w.x, hh); ffma2(ago[2], w.y, hh);
        hh = pk2(h.w, h.w); ffma2(aif[3], w.x, hh); ffma2(ago[3], w.y, hh);
        w = wn; h = hn;
    }
}

__device__ __forceinline__ void act_update(const u64 aif[4], const u64 ago[4],
                                           float c[4], float hv[4]) {
#pragma unroll
    for (int r = 0; r < 4; ++r) {
        float pi, pf, pg, po;
        upk2(aif[r], pi, pf);
        upk2(ago[r], pg, po);
        float iv = fsig(pi);
        float fv = fsig(pf);
        float gv = ftanh(pg);
        float ov = fsig(po);
        c[r]  = fv * c[r] + iv * gv;
        hv[r] = ov * ftanh(c[r]);
    }
}

extern __shared__ float smem[];

__global__ __launch_bounds__(NT, 1) void lstm2_kernel(
    const float* __restrict__ x,
    const float* __restrict__ w_ih0, const float* __restrict__ w_hh0,
    const float* __restrict__ b_ih0, const float* __restrict__ b_hh0,
    const float* __restrict__ w_ih1, const float* __restrict__ w_hh1,
    const float* __restrict__ b_ih1, const float* __restrict__ b_hh1,
    const float* __restrict__ fc_w,  const float* __restrict__ fc_b,
    float* __restrict__ out)
{
    char* sb = (char*)smem;
    const int tid   = threadIdx.x;
    const int bbase = blockIdx.x * BT;

    // ---- stage packed weights: wp[j][k] = (Wi[j][k], Wf, Wg, Wo) ----
    {
        float4* wp0 = (float4*)(sb + OFF_WP0);
        float4* wpA = (float4*)(sb + OFF_WPA);
        float4* wpB = (float4*)(sb + OFF_WPB);
        for (int idx = tid; idx < HID * HID; idx += NT) {
            int jj = idx / HID, kk = idx - jj * HID;
            int r0 = jj * HID + kk;
            wp0[idx] = make_float4(w_hh0[r0], w_hh0[r0 + 50 * HID],
                                   w_hh0[r0 + 100 * HID], w_hh0[r0 + 150 * HID]);
            wpA[idx] = make_float4(w_ih1[r0], w_ih1[r0 + 50 * HID],
                                   w_ih1[r0 + 100 * HID], w_ih1[r0 + 150 * HID]);
            wpB[idx] = make_float4(w_hh1[r0], w_hh1[r0 + 50 * HID],
                                   w_hh1[r0 + 100 * HID], w_hh1[r0 + 150 * HID]);
        }
        float4* b0p = (float4*)(sb + OFF_B0);
        float4* b1p = (float4*)(sb + OFF_B1);
        float4* wxp = (float4*)(sb + OFF_WX);
        float*  fcs = (float*)(sb + OFF_FCW);
        for (int g = tid; g < HID; g += NT) {
            b0p[g] = make_float4(b_ih0[g]       + b_hh0[g],
                                 b_ih0[g + 50]  + b_hh0[g + 50],
                                 b_ih0[g + 100] + b_hh0[g + 100],
                                 b_ih0[g + 150] + b_hh0[g + 150]);
            b1p[g] = make_float4(b_ih1[g]       + b_hh1[g],
                                 b_ih1[g + 50]  + b_hh1[g + 50],
                                 b_ih1[g + 100] + b_hh1[g + 100],
                                 b_ih1[g + 150] + b_hh1[g + 150]);
            wxp[g] = make_float4(w_ih0[g], w_ih0[g + 50],
                                 w_ih0[g + 100], w_ih0[g + 150]);
            fcs[g] = fc_w[g];
        }
        float* hz = (float*)(sb + OFF_H1);
        for (int idx = tid; idx < 6400; idx += NT) hz[idx] = 0.0f;  // h1+h2 bufs
    }
    __syncthreads();

    // ---- per-thread mapping ----
    const int bg = tid & 7;     // batch group: batches 4*bg .. 4*bg+3
    const int j  = tid >> 3;    // hidden unit (0..49)

    u64 b0if, b0go, b1if, b1go, wxif, wxgo;
    {
        float4 t4 = ((float4*)(sb + OFF_B0))[j];
        b0if = pk2(t4.x, t4.y); b0go = pk2(t4.z, t4.w);
        t4 = ((float4*)(sb + OFF_B1))[j];
        b1if = pk2(t4.x, t4.y); b1go = pk2(t4.z, t4.w);
        t4 = ((float4*)(sb + OFF_WX))[j];
        wxif = pk2(t4.x, t4.y); wxgo = pk2(t4.z, t4.w);
    }

    const char* w0p = sb + OFF_WP0 + j * 800;
    const char* wAp = sb + OFF_WPA + j * 800;
    const char* wBp = sb + OFF_WPB + j * 800;
    const char* h1rd = sb + OFF_H1 + bg * 16;
    const char* h2rd = sb + OFF_H2 + bg * 16;
    const char* xrd  = sb + OFF_XS + bg * 16;

    float c1[4] = {0.f, 0.f, 0.f, 0.f};
    float c2[4] = {0.f, 0.f, 0.f, 0.f};
    float h1v[4], h2v[4];

    for (int t = 0; t < TLEN; ++t) {
        // stage 64-step x chunk (coalesced)
        if ((t & 63) == 0) {
            float* xs = (float*)(sb + OFF_XS);
            for (int idx = tid; idx < BT * 64; idx += NT) {
                int b = idx >> 6, tt = idx & 63;
                xs[tt * BT + b] = x[(bbase + b) * TLEN + t + tt];
            }
            __syncthreads();
        }

        const int cur = (t & 1) * HBUF;
        const int nxt = HBUF - cur;

        // ============ layer 1 ============
        u64 aif[4], ago[4];
        {
            float4 xv = *(const float4*)(xrd + (t & 63) * 128);
            u64 hh;
            hh = pk2(xv.x, xv.x); aif[0] = b0if; ffma2(aif[0], wxif, hh);
                                  ago[0] = b0go; ffma2(ago[0], wxgo, hh);
            hh = pk2(xv.y, xv.y); aif[1] = b0if; ffma2(aif[1], wxif, hh);
                                  ago[1] = b0go; ffma2(ago[1], wxgo, hh);
            hh = pk2(xv.z, xv.z); aif[2] = b0if; ffma2(aif[2], wxif, hh);
                                  ago[2] = b0go; ffma2(ago[2], wxgo, hh);
            hh = pk2(xv.w, xv.w); aif[3] = b0if; ffma2(aif[3], wxif, hh);
                                  ago[3] = b0go; ffma2(ago[3], wxgo, hh);
        }
        gemm50(w0p, h1rd + cur, aif, ago);
        act_update(aif, ago, c1, h1v);
        *(float4*)(sb + OFF_H1 + nxt + j * 128 + bg * 16) =
            make_float4(h1v[0], h1v[1], h1v[2], h1v[3]);
        __syncthreads();

        // ============ layer 2 ============
        aif[0] = b1if; aif[1] = b1if; aif[2] = b1if; aif[3] = b1if;
        ago[0] = b1go; ago[1] = b1go; ago[2] = b1go; ago[3] = b1go;
        gemm50(wAp, h1rd + nxt, aif, ago);   // input path: new h1
        gemm50(wBp, h2rd + cur, aif, ago);   // recurrent path: old h2
        act_update(aif, ago, c2, h2v);
        *(float4*)(sb + OFF_H2 + nxt + j * 128 + bg * 16) =
            make_float4(h2v[0], h2v[1], h2v[2], h2v[3]);
        __syncthreads();
    }

    // ---- final FC (last h2 lives in buffer 0 after t=511) ----
    if (tid < BT) {
        const float* h2f = (const float*)(sb + OFF_H2);
        const float* fcs = (const float*)(sb + OFF_FCW);
        float s = fc_b[0];
#pragma unroll 10
        for (int k = 0; k < HID; ++k) s += h2f[k * BT + tid] * fcs[k];
        out[bbase + tid] = s;
    }
}

extern "C" void kernel_launch(void* const* d_in, const int* in_sizes, int n_in,
                              void* d_out, int out_size) {
    const float* x     = (const float*)d_in[0];
    const float* w_ih0 = (const float*)d_in[1];
    const float* w_hh0 = (const float*)d_in[2];
    const float* b_ih0 = (const float*)d_in[3];
    const float* b_hh0 = (const float*)d_in[4];
    const float* w_ih1 = (const float*)d_in[5];
    const float* w_hh1 = (const float*)d_in[6];
    const float* b_ih1 = (const float*)d_in[7];
    const float* b_hh1 = (const float*)d_in[8];
    const float* fc_w  = (const float*)d_in[9];
    const float* fc_b  = (const float*)d_in[10];
    float* out = (float*)d_out;

    cudaFuncSetAttribute(lstm2_kernel,
                         cudaFuncAttributeMaxDynamicSharedMemorySize,
                         SMEM_BYTES);

    lstm2_kernel<<<4096 / BT, NT, SMEM_BYTES>>>(
        x, w_ih0, w_hh0, b_ih0, b_hh0,
        w_ih1, w_hh1, b_ih1, b_hh1, fc_w, fc_b, out);
}